// round 8
// baseline (speedup 1.0000x reference)
#include <cuda_runtime.h>
#include <math.h>

#define T_  256
#define B_  32
#define E_  256
#define H_  512
#define V_  2048
#define TB_ 8192
#define G4H 2048

typedef unsigned long long ull;

// ---------------- static device scratch ----------------
__device__ float g_X[TB_ * 512];                  // [t*B+b][512]
__device__ float g_G[(size_t)T_ * G4H * B_];      // [t][n][b]  (pure ih-dot, no bias)
__device__ float g_Y0[(size_t)TB_ * H_];          // [t*B+b][512]  (layer-1 ih GEMM input)
__device__ float g_Y1[(size_t)TB_ * H_];          // [t][k][b]     (logits GEMM input)
__device__ float g_logits[(size_t)TB_ * V_];
__device__ float g_hbuf[2][2][H_][B_];            // [layer][ping][k][b]
__device__ float g_rowloss[TB_];
__device__ unsigned int g_bar[2];

// ---------------- f32x2 packed helpers ----------------
__device__ __forceinline__ void ffma2(ull& d, ull a, ull b) {
    asm("fma.rn.f32x2 %0, %1, %2, %0;" : "+l"(d) : "l"(a), "l"(b));
}
__device__ __forceinline__ ull pk2(float x, float y) {
    ull r; asm("mov.b64 %0, {%1,%2};" : "=l"(r) : "f"(x), "f"(y)); return r;
}
__device__ __forceinline__ float2 upk(ull v) {
    float2 r; asm("mov.b64 {%0,%1}, %2;" : "=f"(r.x), "=f"(r.y) : "l"(v)); return r;
}

// ---------------- XLA-matched fp32 nonlinearities ----------------
__device__ __forceinline__ float xla_tanhf(float x) {
    float ax = fabsf(x);
    float xc = fminf(fmaxf(x, -9.0f), 9.0f);
    float x2 = __fmul_rn(xc, xc);
    float p = -2.76076847742355e-16f;
    p = __fadd_rn(__fmul_rn(p, x2),  2.00018790482477e-13f);
    p = __fadd_rn(__fmul_rn(p, x2), -8.60467152213735e-11f);
    p = __fadd_rn(__fmul_rn(p, x2),  5.12229709037114e-08f);
    p = __fadd_rn(__fmul_rn(p, x2),  1.48572235717979e-05f);
    p = __fadd_rn(__fmul_rn(p, x2),  6.37261928875436e-04f);
    p = __fadd_rn(__fmul_rn(p, x2),  4.89352455891786e-03f);
    float np = __fmul_rn(xc, p);
    float q = 1.19825839466702e-06f;
    q = __fadd_rn(__fmul_rn(q, x2),  1.18534705686654e-04f);
    q = __fadd_rn(__fmul_rn(q, x2),  2.26843463243900e-03f);
    q = __fadd_rn(__fmul_rn(q, x2),  4.89352518554385e-03f);
    float r = __fdiv_rn(np, q);
    return (ax < 0.0004f) ? x : r;
}
__device__ __forceinline__ float xla_sigmoidf(float x) {
    return __fdiv_rn(1.0f, __fadd_rn(1.0f, expf(-x)));
}

// ---------------- init ----------------
__global__ void init_kernel(const float* __restrict__ h0) {
    int idx = blockIdx.x * 256 + threadIdx.x;
    if (idx < 2) g_bar[idx] = 0u;
    if (idx < 2 * H_ * B_) {
        int l = idx >> 14;
        int rem = idx & 16383;
        int k = rem >> 5, b = rem & 31;
        g_hbuf[l][0][k][b] = h0[(size_t)l * B_ * H_ + (size_t)b * H_ + k];
    }
}

// ---------------- embedding gather ----------------
__global__ void embed_kernel(const int* __restrict__ pc, const int* __restrict__ delta,
                             const float* __restrict__ pc_emb, const float* __restrict__ delta_emb) {
    int r = blockIdx.x;
    int i = threadIdx.x;
    float4* dst = (float4*)(g_X + (size_t)r * 512);
    if (i < 64) dst[i] = ((const float4*)(pc_emb + (size_t)pc[r] * E_))[i];
    else        dst[i] = ((const float4*)(delta_emb + (size_t)delta[r] * E_))[i - 64];
}

// ---------------- ih GEMM: G[t][n][b] = A . W^T, FFMA2 with dup-A in smem ----------------
__global__ void __launch_bounds__(256) gemm_ih_kernel(int which, const float* __restrict__ W) {
    const float* __restrict__ A = which ? g_Y0 : g_X;
    __shared__ ull   As2[16][130];   // dup pairs (a,a)
    __shared__ float Bs[16][132];
    int tid = threadIdx.x;
    int tx = tid & 15, ty = tid >> 4;
    int bn = blockIdx.x * 128;
    int bm = blockIdx.y * 128;

    ull acc2[8][4];
#pragma unroll
    for (int i = 0; i < 8; i++)
#pragma unroll
        for (int j = 0; j < 4; j++) acc2[i][j] = 0ull;

    for (int k0 = 0; k0 < 512; k0 += 16) {
#pragma unroll
        for (int i = 0; i < 2; i++) {
            int f = tid + i * 256;
            int row = f >> 2;
            int c4 = (f & 3) * 4;
            float4 av = *(const float4*)(A + (size_t)(bm + row) * 512 + k0 + c4);
            As2[c4 + 0][row] = pk2(av.x, av.x);
            As2[c4 + 1][row] = pk2(av.y, av.y);
            As2[c4 + 2][row] = pk2(av.z, av.z);
            As2[c4 + 3][row] = pk2(av.w, av.w);
            float4 bv = *(const float4*)(W + (size_t)(bn + row) * 512 + k0 + c4);
            Bs[c4 + 0][row] = bv.x; Bs[c4 + 1][row] = bv.y;
            Bs[c4 + 2][row] = bv.z; Bs[c4 + 3][row] = bv.w;
        }
        __syncthreads();
#pragma unroll
        for (int kk = 0; kk < 16; kk++) {
            ulonglong2 a01 = *(const ulonglong2*)&As2[kk][ty * 8 + 0];
            ulonglong2 a23 = *(const ulonglong2*)&As2[kk][ty * 8 + 2];
            ulonglong2 a45 = *(const ulonglong2*)&As2[kk][ty * 8 + 4];
            ulonglong2 a67 = *(const ulonglong2*)&As2[kk][ty * 8 + 6];
            ulonglong2 b01 = *(const ulonglong2*)&Bs[kk][tx * 8];
            ulonglong2 b23 = *(const ulonglong2*)&Bs[kk][tx * 8 + 4];
            ull ap[8] = {a01.x, a01.y, a23.x, a23.y, a45.x, a45.y, a67.x, a67.y};
#pragma unroll
            for (int mi = 0; mi < 8; mi++) {
                ffma2(acc2[mi][0], ap[mi], b01.x);
                ffma2(acc2[mi][1], ap[mi], b01.y);
                ffma2(acc2[mi][2], ap[mi], b23.x);
                ffma2(acc2[mi][3], ap[mi], b23.y);
            }
        }
        __syncthreads();
    }

    float acc[8][8];
#pragma unroll
    for (int mi = 0; mi < 8; mi++)
#pragma unroll
        for (int jp = 0; jp < 4; jp++) {
            float2 f2 = upk(acc2[mi][jp]);
            acc[mi][2 * jp] = f2.x; acc[mi][2 * jp + 1] = f2.y;
        }

    int m0 = bm + ty * 8;
    int t = m0 >> 5;
    int b0 = m0 & 31;
#pragma unroll
    for (int nj = 0; nj < 8; nj++) {
        int n = bn + tx * 8 + nj;
        size_t base = ((size_t)t * G4H + n) * B_ + b0;
        float4 v0 = make_float4(acc[0][nj], acc[1][nj], acc[2][nj], acc[3][nj]);
        float4 v1 = make_float4(acc[4][nj], acc[5][nj], acc[6][nj], acc[7][nj]);
        *(float4*)(g_G + base) = v0;
        *(float4*)(g_G + base + 4) = v1;
    }
}

// ---------------- persistent LSTM layer: FFMA2, 128 CTAs x 256 thr ----------------
// warp q: hjl=q&3, gbase=(q<4)?0:2; lane: gsel=lane>>4 (gate=gbase+gsel), bp=lane&15 (b=2bp,2bp+1).
__global__ void __launch_bounds__(256) lstm_kernel(const float* __restrict__ Whh,
                                                   const float* __restrict__ c0l,
                                                   int layer, int ylayout,
                                                   float* __restrict__ Y,
                                                   float* __restrict__ dout,
                                                   const float* __restrict__ bih,
                                                   const float* __restrict__ bhh) {
    extern __shared__ char smraw[];
    ulonglong2* h2  = (ulonglong2*)smraw;               // 4096 * 16B = 64KB
    ulonglong2* w2  = (ulonglong2*)(smraw + 65536);     // 4096 * 16B = 64KB
    float2*     ex2 = (float2*)(smraw + 131072);        // 128 * 8B = 1KB

    float* hbuf = &g_hbuf[layer][0][0][0];
    unsigned int* bar = &g_bar[layer];

    int tid = threadIdx.x;
    int lane = tid & 31, q = tid >> 5;
    int hjl = q & 3;
    int gbase = (q < 4) ? 0 : 2;
    int gsel = lane >> 4;
    int bp = lane & 15;
    int g = gbase + gsel;
    int hj = blockIdx.x * 4 + hjl;
    int wrow = hjl * 4 + g;
    int n = g * 512 + hj;
    float bias = __fadd_rn(bih[n], bhh[n]);

    // stage W_hh dup-pairs (once)
    for (int e = tid; e < 4096; e += 256) {
        int row = e >> 8;          // 0..15 : hl = row>>2, gg = row&3
        int k2 = e & 255;
        int gg = row & 3, hl = row >> 2;
        float2 wv = *(const float2*)(Whh + ((size_t)gg * 512 + blockIdx.x * 4 + hl) * 512 + 2 * k2);
        ulonglong2 d;
        d.x = pk2(wv.x, wv.x); d.y = pk2(wv.y, wv.y);
        w2[row * 256 + k2] = d;
    }

    // c state in i-lanes (warps 0-3, lanes 0-15)
    float c0r = 0.0f, c1r = 0.0f;
    if (q < 4 && lane < 16) {
        c0r = c0l[(size_t)(2 * bp) * 512 + hj];
        c1r = c0l[(size_t)(2 * bp + 1) * 512 + hj];
    }
    __syncthreads();

    const ulonglong2* wp = w2 + wrow * 256;
    int ping = 0;
    for (int t = 0; t < 256; t++) {
        // stage h -> interleaved layout [k2][bp]; FULL coverage: 2048 entries x 8 floats
        const float* hsrc = hbuf + ping * 16384;
#pragma unroll 8
        for (int m = tid; m < 2048; m += 256) {
            int k2 = m >> 3, bq = m & 7;
            float4 r0 = *(const float4*)(hsrc + (2 * k2) * 32 + 4 * bq);
            float4 r1 = *(const float4*)(hsrc + (2 * k2 + 1) * 32 + 4 * bq);
            ulonglong2 e0, e1;
            e0.x = pk2(r0.x, r0.y); e0.y = pk2(r1.x, r1.y);
            e1.x = pk2(r0.z, r0.w); e1.y = pk2(r1.z, r1.w);
            h2[k2 * 16 + 2 * bq]     = e0;
            h2[k2 * 16 + 2 * bq + 1] = e1;
        }
        __syncthreads();

        // prefetch G (independent of dot)
        float2 Gv = *(const float2*)(g_G + ((size_t)t * G4H + n) * B_ + 2 * bp);

        // dot: single FFMA2 chain, ascending k
        ull acc = 0ull;
        const ulonglong2* hp = h2 + bp;
#pragma unroll 8
        for (int k2 = 0; k2 < 256; k2++) {
            ulonglong2 wv = wp[k2];
            ulonglong2 hv = hp[k2 * 16];
            ffma2(acc, hv.x, wv.x);
            ffma2(acc, hv.y, wv.y);
        }
        float2 d = upk(acc);
        float p0 = __fadd_rn(__fadd_rn(Gv.x, d.x), bias);
        float p1 = __fadd_rn(__fadd_rn(Gv.y, d.y), bias);

        // f-gate values to i-lanes via shfl (same warp, lane+16)
        float f0 = __shfl_sync(0xffffffffu, p0, lane | 16);
        float f1 = __shfl_sync(0xffffffffu, p1, lane | 16);

        // g,o pre-acts to smem
        if (q >= 4) {
            ex2[(gsel * 4 + hjl) * 16 + bp] = make_float2(p0, p1);
        }
        __syncthreads();

        if (q < 4 && lane < 16) {
            float2 gg = ex2[(0 * 4 + hjl) * 16 + bp];
            float2 oo = ex2[(1 * 4 + hjl) * 16 + bp];
            // b = 2bp
            float ig0 = xla_sigmoidf(p0);
            float fg0 = xla_sigmoidf(f0);
            float tg0 = xla_tanhf(gg.x);
            float og0 = xla_sigmoidf(oo.x);
            c0r = __fadd_rn(__fmul_rn(fg0, c0r), __fmul_rn(ig0, tg0));
            float h0 = __fmul_rn(og0, xla_tanhf(c0r));
            // b = 2bp+1
            float ig1 = xla_sigmoidf(p1);
            float fg1 = xla_sigmoidf(f1);
            float tg1 = xla_tanhf(gg.y);
            float og1 = xla_sigmoidf(oo.y);
            c1r = __fadd_rn(__fmul_rn(fg1, c1r), __fmul_rn(ig1, tg1));
            float h1 = __fmul_rn(og1, xla_tanhf(c1r));

            *(float2*)(hbuf + (ping ^ 1) * 16384 + hj * 32 + 2 * bp) = make_float2(h0, h1);
            if (ylayout) {
                *(float2*)(Y + (size_t)t * 16384 + hj * 32 + 2 * bp) = make_float2(h0, h1);
            } else {
                Y[((size_t)t * 32 + 2 * bp) * 512 + hj]     = h0;
                Y[((size_t)t * 32 + 2 * bp + 1) * 512 + hj] = h1;
            }
            if (t == 255) {
                int b0i = 2 * bp, b1i = 2 * bp + 1;
                dout[81921  + (size_t)layer * 16384 + (size_t)b0i * 512 + hj] = h0;
                dout[81921  + (size_t)layer * 16384 + (size_t)b1i * 512 + hj] = h1;
                dout[114689 + (size_t)layer * 16384 + (size_t)b0i * 512 + hj] = c0r;
                dout[114689 + (size_t)layer * 16384 + (size_t)b1i * 512 + hj] = c1r;
            }
        }
        // grid barrier
        __syncthreads();
        if (tid == 0) {
            __threadfence();
            atomicAdd(bar, 1u);
            unsigned int target = 128u * (unsigned)(t + 1);
            volatile unsigned int* vb = (volatile unsigned int*)bar;
            while (*vb < target) { }
            __threadfence();
        }
        __syncthreads();
        ping ^= 1;
    }
}

// ---------------- cluster-routed projection, FFMA2 + dup-A smem ----------------
__global__ void __launch_bounds__(256) logits_kernel(const int* __restrict__ clusters,
                                                     const float* __restrict__ Wc,
                                                     const float* __restrict__ bc) {
    __shared__ ull   As2[32][36];
    __shared__ float Bs[32][132];
    int tid = threadIdx.x;
    int t = blockIdx.y;
    int c = clusters[t];
    int n0 = blockIdx.x * 128;
    int tm = tid >> 5, tn = tid & 31;

    ull acc2[4][2];
#pragma unroll
    for (int i = 0; i < 4; i++) { acc2[i][0] = 0ull; acc2[i][1] = 0ull; }

    for (int k0 = 0; k0 < 512; k0 += 32) {
        {
            int kk = tid >> 3, mq = tid & 7;
            float4 av = *(const float4*)(g_Y1 + (size_t)t * 16384 + (size_t)(k0 + kk) * 32 + mq * 4);
            As2[kk][mq * 4 + 0] = pk2(av.x, av.x);
            As2[kk][mq * 4 + 1] = pk2(av.y, av.y);
            As2[kk][mq * 4 + 2] = pk2(av.z, av.z);
            As2[kk][mq * 4 + 3] = pk2(av.w, av.w);
        }
#pragma unroll
        for (int i = 0; i < 4; i++) {
            int idx = tid + i * 256;
            int kk = idx >> 5, c4 = (idx & 31) * 4;
            float4 bv = *(const float4*)(Wc + ((size_t)c * 512 + k0 + kk) * 2048 + n0 + c4);
            *(float4*)&Bs[kk][c4] = bv;
        }
        __syncthreads();
#pragma unroll
        for (int kk = 0; kk < 32; kk++) {
            ulonglong2 a01 = *(const ulonglong2*)&As2[kk][tm * 4 + 0];
            ulonglong2 a23 = *(const ulonglong2*)&As2[kk][tm * 4 + 2];
            ulonglong2 bp = *(const ulonglong2*)&Bs[kk][tn * 4];
            ffma2(acc2[0][0], a01.x, bp.x); ffma2(acc2[0][1], a01.x, bp.y);
            ffma2(acc2[1][0], a01.y, bp.x); ffma2(acc2[1][1], a01.y, bp.y);
            ffma2(acc2[2][0], a23.x, bp.x); ffma2(acc2[2][1], a23.x, bp.y);
            ffma2(acc2[3][0], a23.y, bp.x); ffma2(acc2[3][1], a23.y, bp.y);
        }
        __syncthreads();
    }
#pragma unroll
    for (int mi = 0; mi < 4; mi++) {
        float2 x0 = upk(acc2[mi][0]), x1 = upk(acc2[mi][1]);
        int row = t * 32 + tm * 4 + mi;
        int col = n0 + tn * 4;
        float4 bv = *(const float4*)(bc + (size_t)c * 2048 + col);
        float4 v = make_float4(__fadd_rn(x0.x, bv.x), __fadd_rn(x0.y, bv.y),
                               __fadd_rn(x1.x, bv.z), __fadd_rn(x1.y, bv.w));
        *(float4*)(g_logits + (size_t)row * 2048 + col) = v;
    }
}

// ---------------- log-softmax + loss + top-10 per row ----------------
__global__ void __launch_bounds__(256) softmax_topk_kernel(const int* __restrict__ target,
                                                           float* __restrict__ dout) {
    int r = blockIdx.x;
    int tid = threadIdx.x;
    const float* L = g_logits + (size_t)r * 2048;
    float v[8];
#pragma unroll
    for (int j = 0; j < 8; j++) v[j] = L[tid + j * 256];

    __shared__ float  sv[8];
    __shared__ int    si[8];
    __shared__ double sd[8];
    __shared__ float  sbc;

    float m = -INFINITY;
#pragma unroll
    for (int j = 0; j < 8; j++) m = fmaxf(m, v[j]);
#pragma unroll
    for (int o = 16; o > 0; o >>= 1) m = fmaxf(m, __shfl_xor_sync(0xffffffffu, m, o));
    if ((tid & 31) == 0) sv[tid >> 5] = m;
    __syncthreads();
    if (tid == 0) {
        float mm = sv[0];
        for (int w = 1; w < 8; w++) mm = fmaxf(mm, sv[w]);
        sv[0] = mm;
    }
    __syncthreads();
    float M = sv[0];

    float sf[8];
    double s = 0.0;
#pragma unroll
    for (int j = 0; j < 8; j++) {
        sf[j] = __fadd_rn(v[j], -M);
        s += (double)expf(sf[j]);
    }
#pragma unroll
    for (int o = 16; o > 0; o >>= 1) s += __shfl_xor_sync(0xffffffffu, s, o);
    if ((tid & 31) == 0) sd[tid >> 5] = s;
    __syncthreads();
    if (tid == 0) {
        double ss = 0.0;
        for (int w = 0; w < 8; w++) ss += sd[w];
        double logS = log(ss);
        sbc = (float)logS;
        float sft = __fadd_rn(L[target[r]], -M);
        g_rowloss[r] = (float)(logS - (double)sft);
    }
    __syncthreads();
    float logS_f = sbc;

    float qv[8];
#pragma unroll
    for (int j = 0; j < 8; j++) qv[j] = __fadd_rn(sf[j], -logS_f);

    for (int it = 0; it < 10; it++) {
        float bv = -INFINITY;
        int bi = 1 << 30;
#pragma unroll
        for (int j = 0; j < 8; j++) {
            int gi = tid + j * 256;
            if (qv[j] > bv || (qv[j] == bv && gi < bi)) { bv = qv[j]; bi = gi; }
        }
#pragma unroll
        for (int o = 16; o > 0; o >>= 1) {
            float ov = __shfl_xor_sync(0xffffffffu, bv, o);
            int   oi = __shfl_xor_sync(0xffffffffu, bi, o);
            if (ov > bv || (ov == bv && oi < bi)) { bv = ov; bi = oi; }
        }
        if ((tid & 31) == 0) { sv[tid >> 5] = bv; si[tid >> 5] = bi; }
        __syncthreads();
        if (tid == 0) {
            float wv = sv[0]; int wi = si[0];
            for (int w = 1; w < 8; w++)
                if (sv[w] > wv || (sv[w] == wv && si[w] < wi)) { wv = sv[w]; wi = si[w]; }
            si[0] = wi;
            dout[1 + (size_t)r * 10 + it] = (float)wi;
        }
        __syncthreads();
        int wi = si[0];
        if ((wi & 255) == tid) qv[wi >> 8] = -INFINITY;
        __syncthreads();
    }
}

// ---------------- deterministic loss reduction (double) ----------------
__global__ void __launch_bounds__(256) loss_kernel(float* __restrict__ dout) {
    __shared__ double s[256];
    int tid = threadIdx.x;
    double a = 0.0;
    for (int i = 0; i < 32; i++) a += (double)g_rowloss[tid * 32 + i];
    s[tid] = a;
    __syncthreads();
    for (int o = 128; o > 0; o >>= 1) {
        if (tid < o) s[tid] += s[tid + o];
        __syncthreads();
    }
    if (tid == 0) dout[0] = (float)(s[0] / 8192.0);
}

extern "C" void kernel_launch(void* const* d_in, const int* in_sizes, int n_in,
                              void* d_out, int out_size) {
    const int*   pc        = (const int*)d_in[0];
    const int*   delta     = (const int*)d_in[1];
    const int*   clusters  = (const int*)d_in[2];
    const int*   target    = (const int*)d_in[3];
    const float* h0        = (const float*)d_in[4];
    const float* c0        = (const float*)d_in[5];
    const float* pc_emb    = (const float*)d_in[6];
    const float* delta_emb = (const float*)d_in[7];
    const float* w_ih0     = (const float*)d_in[8];
    const float* w_hh0     = (const float*)d_in[9];
    const float* b_ih0     = (const float*)d_in[10];
    const float* b_hh0     = (const float*)d_in[11];
    const float* w_ih1     = (const float*)d_in[12];
    const float* w_hh1     = (const float*)d_in[13];
    const float* b_ih1     = (const float*)d_in[14];
    const float* b_hh1     = (const float*)d_in[15];
    const float* Wc        = (const float*)d_in[16];
    const float* bc        = (const float*)d_in[17];
    float* out = (float*)d_out;

    static int smem_set = 0;
    int lstm_smem = 132096;
    if (!smem_set) {
        cudaFuncSetAttribute(lstm_kernel, cudaFuncAttributeMaxDynamicSharedMemorySize, lstm_smem);
        smem_set = 1;
    }

    float* g_Y0p = nullptr; float* g_Y1p = nullptr;
    cudaGetSymbolAddress((void**)&g_Y0p, g_Y0);
    cudaGetSymbolAddress((void**)&g_Y1p, g_Y1);

    init_kernel<<<128, 256>>>(h0);
    embed_kernel<<<TB_, 128>>>(pc, delta, pc_emb, delta_emb);
    gemm_ih_kernel<<<dim3(16, 64), 256>>>(0, w_ih0);
    lstm_kernel<<<128, 256, lstm_smem>>>(w_hh0, c0, 0, 0, g_Y0p, out, b_ih0, b_hh0);
    gemm_ih_kernel<<<dim3(16, 64), 256>>>(1, w_ih1);
    lstm_kernel<<<128, 256, lstm_smem>>>(w_hh1, c0 + (size_t)B_ * H_, 1, 1, g_Y1p, out, b_ih1, b_hh1);
    logits_kernel<<<dim3(16, 256), 256>>>(clusters, Wc, bc);
    softmax_topk_kernel<<<TB_, 256>>>(target, out);
    loss_kernel<<<1, 256>>>(out);
}